// round 15
// baseline (speedup 1.0000x reference)
#include <cuda_runtime.h>

// LIF neuron scan, round 14: re-validate the ncu-best configuration.
// This is the round-11 kernel verbatim: 4-buffer ring, prefetch distance 2,
// issue-before-wait ordering, original FMA-form LIF step.
//
// Evidence: ncu kernel dur (controlled) ranks this config fastest of all
// rounds (61.7us, DRAM 71.9%); its one elevated bench reading coincided with
// a container session whose other round benched an unrelated kernel at the
// same 75.8us. r12/r13 established that both the barrier reorder and the
// FSEL lif_step are regressions, so neither is included.

#define T_STEPS   100
#define T_VEC     (T_STEPS / 4)        // 25 float4 per row
#define ROWS_CTA  128
#define TILE_V4   (ROWS_CTA * T_VEC)   // 3200 float4 = 50 KB
#define TILE_BYTES (TILE_V4 * 16)
#define RING      4                    // 4 x 50 KB = 200 KB
#define GRID_P    148                  // 1 persistent CTA per SM

__device__ __forceinline__ void cp_async16(float4* smem_dst, const float4* gmem_src) {
    unsigned saddr = (unsigned)__cvta_generic_to_shared(smem_dst);
    asm volatile("cp.async.cg.shared.global [%0], [%1], 16;\n" :: "r"(saddr), "l"(gmem_src));
}
__device__ __forceinline__ void cp_commit() {
    asm volatile("cp.async.commit_group;\n");
}
template <int N>
__device__ __forceinline__ void cp_wait() {
    asm volatile("cp.async.wait_group %0;\n" :: "n"(N));
}

__device__ __forceinline__ void bulk_store(float4* gmem_dst, const float4* smem_src, unsigned bytes) {
    unsigned saddr = (unsigned)__cvta_generic_to_shared(smem_src);
    asm volatile("cp.async.bulk.global.shared::cta.bulk_group [%0], [%1], %2;\n"
                 :: "l"(gmem_dst), "r"(saddr), "r"(bytes) : "memory");
}
__device__ __forceinline__ void bulk_commit() {
    asm volatile("cp.async.bulk.commit_group;\n");
}
template <int N>
__device__ __forceinline__ void bulk_wait() {
    asm volatile("cp.async.bulk.wait_group %0;\n" :: "n"(N) : "memory");
}
__device__ __forceinline__ void fence_async_proxy() {
    asm volatile("fence.proxy.async.shared::cta;\n" ::: "memory");
}

__global__ __launch_bounds__(ROWS_CTA, 1) void lif_kernel(const float4* __restrict__ x,
                                                          float4* __restrict__ out,
                                                          int ntiles) {
    extern __shared__ float4 smem[];              // [RING * TILE_V4]

    const int tid    = threadIdx.x;
    const int stride = gridDim.x;

    const int tile0 = blockIdx.x;
    if (tile0 >= ntiles) return;

    // Prologue: prefetch tiles tile0 and tile0+stride (2 committed groups).
    #pragma unroll
    for (int d = 0; d < 2; ++d) {
        long long t = tile0 + (long long)d * stride;
        if (t < ntiles) {
            const float4* src = x + t * TILE_V4;
            float4* dst = smem + d * TILE_V4;
            #pragma unroll
            for (int i = 0; i < T_VEC; ++i)
                cp_async16(&dst[tid + ROWS_CTA * i], &src[tid + ROWS_CTA * i]);
        }
        cp_commit();
    }

    int j = 0;
    for (long long tile = tile0; tile < ntiles; tile += stride, ++j) {
        float4* cur = smem + (j & 3) * TILE_V4;
        float4* pre = smem + ((j + 2) & 3) * TILE_V4;

        // Free the prefetch target: its tile (j-2) store is the oldest of the
        // (at most) 2 outstanding bulk stores.
        if (tid == 0) bulk_wait<1>();
        __syncthreads();

        // Issue load(k+2) BEFORE waiting on load(k) -- keeps the read stream
        // non-empty across the stall. ALWAYS commit (empty group in the tail)
        // to keep the group-count invariant for cp_wait<2>.
        long long t2 = tile + 2LL * stride;
        if (t2 < ntiles) {
            const float4* src = x + t2 * TILE_V4;
            #pragma unroll
            for (int i = 0; i < T_VEC; ++i)
                cp_async16(&pre[tid + ROWS_CTA * i], &src[tid + ROWS_CTA * i]);
        }
        cp_commit();

        // <=2 groups outstanding leaves only (k+1),(k+2): load(k) has landed.
        cp_wait<2>();
        __syncthreads();

        // ---- Compute: serial LIF scan of this thread's row, in place ----
        const float decay = 0.5f;
        const float vth   = 0.5f;
        float v = 0.0f;
        float4* __restrict__ row = cur + tid * T_VEC;

        #pragma unroll
        for (int i = 0; i < T_VEC; ++i) {
            float4 xi = row[i];
            float4 so;

            v = fmaf(v, decay, xi.x);
            so.x = (v > vth) ? 1.0f : 0.0f;
            v = fmaf(so.x, -vth, v);

            v = fmaf(v, decay, xi.y);
            so.y = (v > vth) ? 1.0f : 0.0f;
            v = fmaf(so.y, -vth, v);

            v = fmaf(v, decay, xi.z);
            so.z = (v > vth) ? 1.0f : 0.0f;
            v = fmaf(so.z, -vth, v);

            v = fmaf(v, decay, xi.w);
            so.w = (v > vth) ? 1.0f : 0.0f;
            v = fmaf(so.w, -vth, v);

            row[i] = so;
        }

        // Order generic smem writes before the async-proxy read, then
        // fire-and-forget the 50 KB tile store.
        fence_async_proxy();
        __syncthreads();
        if (tid == 0) {
            bulk_store(out + tile * TILE_V4, cur, TILE_BYTES);
            bulk_commit();
        }
    }

    // Drain outstanding bulk stores before exit.
    if (tid == 0) bulk_wait<0>();
}

extern "C" void kernel_launch(void* const* d_in, const int* in_sizes, int n_in,
                              void* d_out, int out_size) {
    const float4* x = (const float4*)d_in[0];
    float4* out = (float4*)d_out;

    int n_rows = in_sizes[0] / T_STEPS;          // 524288
    int ntiles = n_rows / ROWS_CTA;              // 4096

    size_t smem_bytes = (size_t)RING * TILE_V4 * sizeof(float4);   // 200 KB
    static bool attr_set = false;
    if (!attr_set) {
        cudaFuncSetAttribute(lif_kernel, cudaFuncAttributeMaxDynamicSharedMemorySize,
                             (int)smem_bytes);
        attr_set = true;
    }
    int grid = ntiles < GRID_P ? ntiles : GRID_P;
    lif_kernel<<<grid, ROWS_CTA, smem_bytes>>>(x, out, ntiles);
}